// round 14
// baseline (speedup 1.0000x reference)
#include <cuda_runtime.h>
#include <cstdint>
#include <math.h>

// Problem constants
#define BB   64
#define TT   128
#define EE   256
#define HH   256
#define BT   (BB*TT)        // 8192

// Scratch input-drive buffer (level-0 only; level-1 drive is computed in-scan).
__device__ float g_xp[BT * HH];

typedef unsigned long long u64t;

__device__ __forceinline__ u64t pk2(float x, float y) {
    u64t r; asm("mov.b64 %0, {%1,%2};" : "=l"(r) : "f"(x), "f"(y)); return r;
}
__device__ __forceinline__ void fma2(u64t& d, u64t a, u64t b) {
    asm("fma.rn.f32x2 %0, %1, %2, %0;" : "+l"(d) : "l"(a), "l"(b));
}
__device__ __forceinline__ void upk2(float& x, float& y, u64t v) {
    asm("mov.b64 {%0,%1}, %2;" : "=f"(x), "=f"(y) : "l"(v));
}

// ---------------------------------------------------------------------------
// GEMM (unchanged R13): g_xp[m,n] = sum_k A[row(m),k]*W[n,k] + bias[n]
//   128x128 tile, 8x8 micro-tile, K-chunks of 32, double-buffered LDG, f32x2.
// ---------------------------------------------------------------------------
__global__ __launch_bounds__(256) void gemm_xp(
    const float* __restrict__ A, const int* __restrict__ rowidx, int astride,
    const float* __restrict__ W, const float* __restrict__ bias)
{
    __shared__ float As[32][136];
    __shared__ float Bs[32][136];

    const int m0  = blockIdx.x * 128;
    const int n0  = blockIdx.y * 128;
    const int tid = threadIdx.x;
    const int tx  = tid & 15;
    const int ty  = tid >> 4;

    const int lrow = tid >> 1;
    const int lkq  = (tid & 1) << 4;
    const int marow = m0 + lrow;
    const int arow  = rowidx ? rowidx[marow] : marow;
    const float* apt = A + (size_t)arow * astride + lkq;
    const float* bpt = W + (size_t)(n0 + lrow) * 256 + lkq;

    float4 apf[4], bpf[4];
    #pragma unroll
    for (int c = 0; c < 4; c++) {
        apf[c] = *(const float4*)(apt + 4 * c);
        bpf[c] = *(const float4*)(bpt + 4 * c);
    }

    u64t acc[8][4] = {};

    for (int k0 = 0; k0 < 256; k0 += 32) {
        #pragma unroll
        for (int c = 0; c < 4; c++) {
            As[lkq + 4 * c + 0][lrow] = apf[c].x;
            As[lkq + 4 * c + 1][lrow] = apf[c].y;
            As[lkq + 4 * c + 2][lrow] = apf[c].z;
            As[lkq + 4 * c + 3][lrow] = apf[c].w;
            Bs[lkq + 4 * c + 0][lrow] = bpf[c].x;
            Bs[lkq + 4 * c + 1][lrow] = bpf[c].y;
            Bs[lkq + 4 * c + 2][lrow] = bpf[c].z;
            Bs[lkq + 4 * c + 3][lrow] = bpf[c].w;
        }
        __syncthreads();

        if (k0 < 224) {
            #pragma unroll
            for (int c = 0; c < 4; c++) {
                apf[c] = *(const float4*)(apt + k0 + 32 + 4 * c);
                bpf[c] = *(const float4*)(bpt + k0 + 32 + 4 * c);
            }
        }

        #pragma unroll
        for (int kk = 0; kk < 32; kk++) {
            ulonglong2 aq0 = *(const ulonglong2*)&As[kk][ty << 2];
            ulonglong2 aq1 = *(const ulonglong2*)&As[kk][64 + (ty << 2)];
            float4 bf0 = *(const float4*)&Bs[kk][tx << 2];
            float4 bf1 = *(const float4*)&Bs[kk][64 + (tx << 2)];

            u64t bd[8];
            bd[0] = pk2(bf0.x, bf0.x); bd[1] = pk2(bf0.y, bf0.y);
            bd[2] = pk2(bf0.z, bf0.z); bd[3] = pk2(bf0.w, bf0.w);
            bd[4] = pk2(bf1.x, bf1.x); bd[5] = pk2(bf1.y, bf1.y);
            bd[6] = pk2(bf1.z, bf1.z); bd[7] = pk2(bf1.w, bf1.w);

            #pragma unroll
            for (int jx = 0; jx < 8; jx++) {
                fma2(acc[jx][0], bd[jx], aq0.x);
                fma2(acc[jx][1], bd[jx], aq0.y);
                fma2(acc[jx][2], bd[jx], aq1.x);
                fma2(acc[jx][3], bd[jx], aq1.y);
            }
        }
        __syncthreads();
    }

    float4 bv0 = *(const float4*)(bias + n0 + (tx << 2));
    float4 bv1 = *(const float4*)(bias + n0 + 64 + (tx << 2));

    #pragma unroll
    for (int p = 0; p < 4; p++) {
        const int rbase = ((p >> 1) << 6) + (ty << 2) + ((p & 1) << 1);
        float v0[8], v1[8];
        #pragma unroll
        for (int jx = 0; jx < 8; jx++)
            upk2(v0[jx], v1[jx], acc[jx][p]);

        float4 o;
        float* d0 = g_xp + (size_t)(m0 + rbase) * 256 + n0;
        o.x = v0[0] + bv0.x; o.y = v0[1] + bv0.y;
        o.z = v0[2] + bv0.z; o.w = v0[3] + bv0.w;
        *(float4*)(d0 + (tx << 2)) = o;
        o.x = v0[4] + bv1.x; o.y = v0[5] + bv1.y;
        o.z = v0[6] + bv1.z; o.w = v0[7] + bv1.w;
        *(float4*)(d0 + 64 + (tx << 2)) = o;

        float* d1 = d0 + 256;
        o.x = v1[0] + bv0.x; o.y = v1[1] + bv0.y;
        o.z = v1[2] + bv0.z; o.w = v1[3] + bv0.w;
        *(float4*)(d1 + (tx << 2)) = o;
        o.x = v1[4] + bv1.x; o.y = v1[5] + bv1.y;
        o.z = v1[6] + bv1.z; o.w = v1[7] + bv1.w;
        *(float4*)(d1 + 64 + (tx << 2)) = o;
    }
}

// ---------------------------------------------------------------------------
// COMBINED two-level LTC scan. 4-CTA clusters, 32 clusters, 2 batch/cluster.
// Level 1 runs ONE STEP BEHIND level 0 inside the same loop:
//   step t:  h0(t)   = F0(h0(t-1), xp0(t))
//            u(t-1)  = W_in1 @ h0(t-1) + b1          (h0(t-1) in read buf)
//            h1(t-1) = F1(h1(t-2), u(t-1))           (h1(t-2) in read buf)
// Exchange block per rank per step: [64 h0b0 | 64 h0b1 | 64 h1b0 | 64 h1b1]
// = 1024 B via the same 3 bulk DSMEM copies / tx mbarrier as the champion.
// h1(-1)=0 falls out of buffer zero-init (h1 region untouched at t=0).
// Epilogue computes h1(127) locally. One kernel, 129 sequential steps total
// instead of 256.
// ---------------------------------------------------------------------------
#define CS    4
#define BLK2  264    // floats per rank block: 256 data + 8 pad

__device__ __forceinline__ uint32_t smem_u32(const void* p) {
    return (uint32_t)__cvta_generic_to_shared(p);
}
__device__ __forceinline__ float hsum2(u64t v) {
    float a, b; asm("mov.b64 {%0,%1}, %2;" : "=f"(a), "=f"(b) : "l"(v));
    return a + b;
}
__device__ __forceinline__ float tanh_fast(float x) {
    float y; asm("tanh.approx.f32 %0, %1;" : "=f"(y) : "f"(x)); return y;
}
__device__ __forceinline__ void mbar_wait(uint32_t mb, uint32_t par) {
    asm volatile(
        "{ .reg .pred p;\n\t"
        "WAIT_%=:\n\t"
        "  mbarrier.try_wait.parity.acquire.cluster.shared::cta.b64 p, [%0], %1, 0x989680;\n\t"
        "  @!p bra WAIT_%=;\n\t"
        "}" :: "r"(mb), "r"(par) : "memory");
}

// GEMV helper: 64-k slice, two batch streams from SMEM, weights in regs.
#define GEMV64(SUM0, SUM1, WREG, P0, P1)                                   \
    do {                                                                   \
        u64t _a0 = 0, _a1 = 0, _c0 = 0, _c1 = 0;                           \
        _Pragma("unroll")                                                  \
        for (int _ii = 0; _ii < 16; _ii++) {                               \
            ulonglong2 _v0 = (P0)[_ii];                                    \
            ulonglong2 _v1 = (P1)[_ii];                                    \
            fma2(_a0, (WREG)[2 * _ii + 0], _v0.x);                         \
            fma2(_a1, (WREG)[2 * _ii + 1], _v0.y);                         \
            fma2(_c0, (WREG)[2 * _ii + 0], _v1.x);                         \
            fma2(_c1, (WREG)[2 * _ii + 1], _v1.y);                         \
        }                                                                  \
        SUM0 = hsum2(_a0) + hsum2(_a1);                                    \
        SUM1 = hsum2(_c0) + hsum2(_c1);                                    \
        SUM0 += __shfl_xor_sync(0xffffffffu, SUM0, 8);                     \
        SUM0 += __shfl_xor_sync(0xffffffffu, SUM0, 16);                    \
        SUM1 += __shfl_xor_sync(0xffffffffu, SUM1, 8);                     \
        SUM1 += __shfl_xor_sync(0xffffffffu, SUM1, 16);                    \
    } while (0)

__global__ void __cluster_dims__(CS, 1, 1) __launch_bounds__(256, 1)
ltc_scan2(const float* __restrict__ Wr0, const float* __restrict__ M0,
          const float* __restrict__ T0,
          const float* __restrict__ Wr1, const float* __restrict__ M1,
          const float* __restrict__ T1,
          const float* __restrict__ Wi1, const float* __restrict__ B1,
          float* __restrict__ out)
{
    __shared__ __align__(16) float hb[3][CS][BLK2];
    __shared__ u64t mbar[2];

    uint32_t rank;
    asm("mov.u32 %0, %%cluster_ctarank;" : "=r"(rank));
    const int cl = blockIdx.x / CS;
    const int b0 = cl * 2;
    const int b1 = b0 + 1;

    const int tid  = threadIdx.x;
    const int lane = tid & 31;
    const int warp = tid >> 5;
    const int jl   = lane & 7;
    const int ks   = lane >> 3;
    const int j    = warp * 8 + jl;
    const int jf   = (int)rank * 64 + j;

    const uint32_t mb_u32[2] = { smem_u32(&mbar[0]), smem_u32(&mbar[1]) };
    if (tid == 0) {
        asm volatile("mbarrier.init.shared.b64 [%0], 1;" :: "r"(mb_u32[0]) : "memory");
        asm volatile("mbarrier.init.shared.b64 [%0], 1;" :: "r"(mb_u32[1]) : "memory");
    }

    for (int e = tid; e < 3 * CS * BLK2; e += 256)
        ((float*)hb)[e] = 0.f;

    int32_t dsd[CS];
    #pragma unroll
    for (int c = 0; c < CS; c++) {
        uint32_t ra;
        asm("mapa.shared::cluster.u32 %0, %1, %2;" : "=r"(ra) : "r"(mb_u32[0]), "r"(c));
        dsd[c] = (int32_t)(ra - mb_u32[0]);
    }

    // Three weight slices in registers, each k in [ks*64, ks*64+64).
    u64t wa0[32], wa1[32], wi[32];
    {
        const float4* wr = (const float4*)(Wr0 + (size_t)jf * HH + ks * 64);
        const float4* mr = (const float4*)(M0  + (size_t)jf * HH + ks * 64);
        #pragma unroll
        for (int ii = 0; ii < 16; ii++) {
            float4 wv = __ldg(wr + ii);
            float4 mv = __ldg(mr + ii);
            wa0[2 * ii + 0] = pk2(wv.x * mv.x, wv.y * mv.y);
            wa0[2 * ii + 1] = pk2(wv.z * mv.z, wv.w * mv.w);
        }
        wr = (const float4*)(Wr1 + (size_t)jf * HH + ks * 64);
        mr = (const float4*)(M1  + (size_t)jf * HH + ks * 64);
        #pragma unroll
        for (int ii = 0; ii < 16; ii++) {
            float4 wv = __ldg(wr + ii);
            float4 mv = __ldg(mr + ii);
            wa1[2 * ii + 0] = pk2(wv.x * mv.x, wv.y * mv.y);
            wa1[2 * ii + 1] = pk2(wv.z * mv.z, wv.w * mv.w);
        }
        wr = (const float4*)(Wi1 + (size_t)jf * HH + ks * 64);
        #pragma unroll
        for (int ii = 0; ii < 16; ii++) {
            float4 wv = __ldg(wr + ii);
            wi[2 * ii + 0] = pk2(wv.x, wv.y);
            wi[2 * ii + 1] = pk2(wv.z, wv.w);
        }
    }

    const float invtau0 = 1.0f / (log1pf(expf(T0[jf])) + 0.1f);
    const float invtau1 = 1.0f / (log1pf(expf(T1[jf])) + 0.1f);
    const float bias1   = __ldg(B1 + jf);

    const float* xp0 = g_xp + (size_t)(b0 * TT) * HH + jf;
    const float* xp1 = g_xp + (size_t)(b1 * TT) * HH + jf;
    float* o00 = out + (size_t)(b0 * TT) * 512 + jf;         // level0, b0
    float* o01 = out + (size_t)(b1 * TT) * 512 + jf;         // level0, b1
    float* o10 = out + (size_t)(b0 * TT) * 512 + 256 + jf;   // level1, b0
    float* o11 = out + (size_t)(b1 * TT) * 512 + 256 + jf;   // level1, b1

    __syncthreads();
    asm volatile("barrier.cluster.arrive.aligned;" ::: "memory");
    asm volatile("barrier.cluster.wait.aligned;"   ::: "memory");

    float xq0 = __ldg(xp0);
    float xq1 = __ldg(xp1);

    int wb = 0, rb = 2;

    for (int t = 0; t < TT; t++) {
        const uint32_t mbx = mb_u32[t & 1];
        if (tid == 0)
            asm volatile("mbarrier.arrive.expect_tx.shared.b64 _, [%0], 3072;"
                         :: "r"(mbx) : "memory");

        const float* rblk = &hb[rb][rank][0];
        const float h0oa = rblk[j];            // h0(t-1) b0
        const float h0ob = rblk[64 + j];       // h0(t-1) b1
        const float h1oa = rblk[128 + j];      // h1(t-2) b0
        const float h1ob = rblk[192 + j];      // h1(t-2) b1

        const ulonglong2* p00 = (const ulonglong2*)(&hb[rb][ks][0]);    // h0 b0
        const ulonglong2* p01 = (const ulonglong2*)(&hb[rb][ks][64]);   // h0 b1
        const ulonglong2* p10 = (const ulonglong2*)(&hb[rb][ks][128]);  // h1 b0
        const ulonglong2* p11 = (const ulonglong2*)(&hb[rb][ks][192]);  // h1 b1

        // Level-0 recurrence pre-activation (critical path).
        float s0, s1;
        GEMV64(s0, s1, wa0, p00, p01);

        float hn0a = fmaf(tanh_fast(s0 + xq0) - h0oa, invtau0, h0oa);
        float hn0b = fmaf(tanh_fast(s1 + xq1) - h0ob, invtau0, h0ob);

        // Level-1 drive + recurrence (lagged one step; same read buffer).
        float u0, u1, r0, r1, hn1a = 0.f, hn1b = 0.f;
        if (t > 0) {
            GEMV64(u0, u1, wi, p00, p01);     // W_in1 @ h0(t-1)
            GEMV64(r0, r1, wa1, p10, p11);    // Wr1m @ h1(t-2)
            hn1a = fmaf(tanh_fast(r0 + u0 + bias1) - h1oa, invtau1, h1oa);
            hn1b = fmaf(tanh_fast(r1 + u1 + bias1) - h1ob, invtau1, h1ob);
        }

        float* wblk = &hb[wb][rank][0];
        if (ks == 0) {
            wblk[j]      = hn0a;
            wblk[64 + j] = hn0b;
        }
        if (ks == 1 && t > 0) {
            wblk[128 + j] = hn1a;
            wblk[192 + j] = hn1b;
        }
        __syncthreads();

        if (tid < 3) {
            asm volatile("fence.proxy.async.shared::cta;" ::: "memory");
            const uint32_t src  = smem_u32(wblk);
            const int      peer = ((int)rank + tid + 1) & 3;
            asm volatile(
                "cp.async.bulk.shared::cluster.shared::cta.mbarrier::complete_tx::bytes "
                "[%0], [%1], 1024, [%2];"
                :: "r"(src + dsd[peer]), "r"(src), "r"(mbx + dsd[peer])
                : "memory");
        }

        // Off-critical-path stores + prefetch while the copies fly.
        if (ks == 2) o00[(size_t)t * 512] = hn0a;
        if (ks == 3) o01[(size_t)t * 512] = hn0b;
        if (t > 0) {
            if (ks == 0) o10[(size_t)(t - 1) * 512] = hn1a;
            if (ks == 1) o11[(size_t)(t - 1) * 512] = hn1b;
        }
        if (t + 1 < TT) {
            xq0 = __ldg(xp0 + (size_t)(t + 1) * HH);
            xq1 = __ldg(xp1 + (size_t)(t + 1) * HH);
        }

        mbar_wait(mbx, (uint32_t)((t >> 1) & 1));

        rb = wb;
        wb = (wb == 2) ? 0 : wb + 1;
    }

    // Epilogue: h1(127) from h0(127), h1(126) — both in the last read buffer.
    {
        const float* rblk = &hb[rb][rank][0];
        const float h1oa = rblk[128 + j];
        const float h1ob = rblk[192 + j];
        const ulonglong2* p00 = (const ulonglong2*)(&hb[rb][ks][0]);
        const ulonglong2* p01 = (const ulonglong2*)(&hb[rb][ks][64]);
        const ulonglong2* p10 = (const ulonglong2*)(&hb[rb][ks][128]);
        const ulonglong2* p11 = (const ulonglong2*)(&hb[rb][ks][192]);

        float u0, u1, r0, r1;
        GEMV64(u0, u1, wi, p00, p01);
        GEMV64(r0, r1, wa1, p10, p11);
        float hn1a = fmaf(tanh_fast(r0 + u0 + bias1) - h1oa, invtau1, h1oa);
        float hn1b = fmaf(tanh_fast(r1 + u1 + bias1) - h1ob, invtau1, h1ob);
        if (ks == 0) o10[(size_t)(TT - 1) * 512] = hn1a;
        if (ks == 1) o11[(size_t)(TT - 1) * 512] = hn1b;
    }

    // Nobody exits while peers' bulk reads of our SMEM may be in flight.
    asm volatile("barrier.cluster.arrive.aligned;" ::: "memory");
    asm volatile("barrier.cluster.wait.aligned;"   ::: "memory");
}

// ---------------------------------------------------------------------------
// Launch: gemm(xp0) -> combined 2-level scan (129 sequential steps total)
// ---------------------------------------------------------------------------
extern "C" void kernel_launch(void* const* d_in, const int* in_sizes, int n_in,
                              void* d_out, int out_size)
{
    const int*   tokens = (const int*)  d_in[0];
    const float* emb    = (const float*)d_in[1];
    const float* W_in0  = (const float*)d_in[2];
    const float* W_rec0 = (const float*)d_in[3];
    const float* b0     = (const float*)d_in[4];
    const float* tau0   = (const float*)d_in[5];
    const float* mask0  = (const float*)d_in[6];
    const float* W_in1  = (const float*)d_in[7];
    const float* W_rec1 = (const float*)d_in[8];
    const float* b1     = (const float*)d_in[9];
    const float* tau1   = (const float*)d_in[10];
    const float* mask1  = (const float*)d_in[11];
    float* out = (float*)d_out;

    (void)in_sizes; (void)n_in; (void)out_size;

    dim3 ggrid(BT / 128, HH / 128);   // 64 x 2 = 128 CTAs (one wave)

    gemm_xp<<<ggrid, 256>>>(emb, tokens, EE, W_in0, b0);
    ltc_scan2<<<128, 256>>>(W_rec0, mask0, tau0,
                            W_rec1, mask1, tau1,
                            W_in1, b1, out);
}

// round 15
// speedup vs baseline: 1.5368x; 1.5368x over previous
#include <cuda_runtime.h>
#include <cstdint>
#include <math.h>

// Problem constants
#define BB   64
#define TT   128
#define EE   256
#define HH   256
#define BT   (BB*TT)        // 8192

// Scratch input-drive buffer (level-0 only; level-1 drive computed in-scan).
__device__ float g_xp[BT * HH];

typedef unsigned long long u64t;

__device__ __forceinline__ u64t pk2(float x, float y) {
    u64t r; asm("mov.b64 %0, {%1,%2};" : "=l"(r) : "f"(x), "f"(y)); return r;
}
__device__ __forceinline__ void fma2(u64t& d, u64t a, u64t b) {
    asm("fma.rn.f32x2 %0, %1, %2, %0;" : "+l"(d) : "l"(a), "l"(b));
}
__device__ __forceinline__ void upk2(float& x, float& y, u64t v) {
    asm("mov.b64 {%0,%1}, %2;" : "=f"(x), "=f"(y) : "l"(v));
}

// ---------------------------------------------------------------------------
// GEMM (unchanged R13): g_xp[m,n] = sum_k A[row(m),k]*W[n,k] + bias[n]
// ---------------------------------------------------------------------------
__global__ __launch_bounds__(256) void gemm_xp(
    const float* __restrict__ A, const int* __restrict__ rowidx, int astride,
    const float* __restrict__ W, const float* __restrict__ bias)
{
    __shared__ float As[32][136];
    __shared__ float Bs[32][136];

    const int m0  = blockIdx.x * 128;
    const int n0  = blockIdx.y * 128;
    const int tid = threadIdx.x;
    const int tx  = tid & 15;
    const int ty  = tid >> 4;

    const int lrow = tid >> 1;
    const int lkq  = (tid & 1) << 4;
    const int marow = m0 + lrow;
    const int arow  = rowidx ? rowidx[marow] : marow;
    const float* apt = A + (size_t)arow * astride + lkq;
    const float* bpt = W + (size_t)(n0 + lrow) * 256 + lkq;

    float4 apf[4], bpf[4];
    #pragma unroll
    for (int c = 0; c < 4; c++) {
        apf[c] = *(const float4*)(apt + 4 * c);
        bpf[c] = *(const float4*)(bpt + 4 * c);
    }

    u64t acc[8][4] = {};

    for (int k0 = 0; k0 < 256; k0 += 32) {
        #pragma unroll
        for (int c = 0; c < 4; c++) {
            As[lkq + 4 * c + 0][lrow] = apf[c].x;
            As[lkq + 4 * c + 1][lrow] = apf[c].y;
            As[lkq + 4 * c + 2][lrow] = apf[c].z;
            As[lkq + 4 * c + 3][lrow] = apf[c].w;
            Bs[lkq + 4 * c + 0][lrow] = bpf[c].x;
            Bs[lkq + 4 * c + 1][lrow] = bpf[c].y;
            Bs[lkq + 4 * c + 2][lrow] = bpf[c].z;
            Bs[lkq + 4 * c + 3][lrow] = bpf[c].w;
        }
        __syncthreads();

        if (k0 < 224) {
            #pragma unroll
            for (int c = 0; c < 4; c++) {
                apf[c] = *(const float4*)(apt + k0 + 32 + 4 * c);
                bpf[c] = *(const float4*)(bpt + k0 + 32 + 4 * c);
            }
        }

        #pragma unroll
        for (int kk = 0; kk < 32; kk++) {
            ulonglong2 aq0 = *(const ulonglong2*)&As[kk][ty << 2];
            ulonglong2 aq1 = *(const ulonglong2*)&As[kk][64 + (ty << 2)];
            float4 bf0 = *(const float4*)&Bs[kk][tx << 2];
            float4 bf1 = *(const float4*)&Bs[kk][64 + (tx << 2)];

            u64t bd[8];
            bd[0] = pk2(bf0.x, bf0.x); bd[1] = pk2(bf0.y, bf0.y);
            bd[2] = pk2(bf0.z, bf0.z); bd[3] = pk2(bf0.w, bf0.w);
            bd[4] = pk2(bf1.x, bf1.x); bd[5] = pk2(bf1.y, bf1.y);
            bd[6] = pk2(bf1.z, bf1.z); bd[7] = pk2(bf1.w, bf1.w);

            #pragma unroll
            for (int jx = 0; jx < 8; jx++) {
                fma2(acc[jx][0], bd[jx], aq0.x);
                fma2(acc[jx][1], bd[jx], aq0.y);
                fma2(acc[jx][2], bd[jx], aq1.x);
                fma2(acc[jx][3], bd[jx], aq1.y);
            }
        }
        __syncthreads();
    }

    float4 bv0 = *(const float4*)(bias + n0 + (tx << 2));
    float4 bv1 = *(const float4*)(bias + n0 + 64 + (tx << 2));

    #pragma unroll
    for (int p = 0; p < 4; p++) {
        const int rbase = ((p >> 1) << 6) + (ty << 2) + ((p & 1) << 1);
        float v0[8], v1[8];
        #pragma unroll
        for (int jx = 0; jx < 8; jx++)
            upk2(v0[jx], v1[jx], acc[jx][p]);

        float4 o;
        float* d0 = g_xp + (size_t)(m0 + rbase) * 256 + n0;
        o.x = v0[0] + bv0.x; o.y = v0[1] + bv0.y;
        o.z = v0[2] + bv0.z; o.w = v0[3] + bv0.w;
        *(float4*)(d0 + (tx << 2)) = o;
        o.x = v0[4] + bv1.x; o.y = v0[5] + bv1.y;
        o.z = v0[6] + bv1.z; o.w = v0[7] + bv1.w;
        *(float4*)(d0 + 64 + (tx << 2)) = o;

        float* d1 = d0 + 256;
        o.x = v1[0] + bv0.x; o.y = v1[1] + bv0.y;
        o.z = v1[2] + bv0.z; o.w = v1[3] + bv0.w;
        *(float4*)(d1 + (tx << 2)) = o;
        o.x = v1[4] + bv1.x; o.y = v1[5] + bv1.y;
        o.z = v1[6] + bv1.z; o.w = v1[7] + bv1.w;
        *(float4*)(d1 + 64 + (tx << 2)) = o;
    }
}

// ---------------------------------------------------------------------------
// Warp-specialized combined two-level LTC scan.
// 4-CTA clusters, 32 clusters, 2 batch/cluster, 384 threads/CTA:
//   warps 0-7  : level-0 chain (R13 structure, wa0 in registers)
//   warps 8-11 : level-1 chain, ONE STEP BEHIND, concurrently:
//                h1(t-1) = F1(h1(t-2), Wi1@h0(t-1) + b1)  [both in read buf]
//                weights Wi1 / Wr1*m1 in SMEM (packed [kq][j] ulonglong2 —
//                8-lane phases read 128B contiguous: conflict-free)
// Exchange block/rank/step: [64 h0b0|64 h0b1|64 h1b0|64 h1b1] = 1024 B via
// 3 bulk DSMEM copies + tx mbarrier (3072 B), 2 alternating barriers,
// 3-buffer rotation. h1(-1)=0 via buffer zero-init; epilogue does h1(127).
// 129 sequential steps chip-wide instead of 256.
// ---------------------------------------------------------------------------
#define CS    4
#define BLK2  264    // floats per rank block: 256 data + 8 pad
#define NT    384

struct SmS {
    float      hb[3][CS][BLK2];   // 50688 B
    u64t       mbar[2];           // 16 B
    ulonglong2 wqi[64][64];       // 65536 B : Wi1 packed, [kq][j]
    ulonglong2 wqa[64][64];       // 65536 B : Wr1*m1 packed
};
#define SMEM_SZ ((int)sizeof(SmS))

__device__ __forceinline__ uint32_t smem_u32(const void* p) {
    return (uint32_t)__cvta_generic_to_shared(p);
}
__device__ __forceinline__ float hsum2(u64t v) {
    float a, b; asm("mov.b64 {%0,%1}, %2;" : "=f"(a), "=f"(b) : "l"(v));
    return a + b;
}
__device__ __forceinline__ float tanh_fast(float x) {
    float y; asm("tanh.approx.f32 %0, %1;" : "=f"(y) : "f"(x)); return y;
}
__device__ __forceinline__ void mbar_wait(uint32_t mb, uint32_t par) {
    asm volatile(
        "{ .reg .pred p;\n\t"
        "WAIT_%=:\n\t"
        "  mbarrier.try_wait.parity.acquire.cluster.shared::cta.b64 p, [%0], %1, 0x989680;\n\t"
        "  @!p bra WAIT_%=;\n\t"
        "}" :: "r"(mb), "r"(par) : "memory");
}

__global__ void __cluster_dims__(CS, 1, 1) __launch_bounds__(NT, 1)
ltc_scan2(const float* __restrict__ Wr0, const float* __restrict__ M0,
          const float* __restrict__ T0,
          const float* __restrict__ Wr1, const float* __restrict__ M1,
          const float* __restrict__ T1,
          const float* __restrict__ Wi1, const float* __restrict__ B1,
          float* __restrict__ out)
{
    extern __shared__ __align__(16) char smraw[];
    SmS* S = (SmS*)smraw;

    uint32_t rank;
    asm("mov.u32 %0, %%cluster_ctarank;" : "=r"(rank));
    const int cl = blockIdx.x / CS;
    const int b0 = cl * 2;
    const int b1 = b0 + 1;

    const int  tid  = threadIdx.x;
    const int  lane = tid & 31;
    const int  warp = tid >> 5;
    const bool isL0 = warp < 8;

    // Level-0 lane layout (warps 0-7): 8 neurons/warp, 4 k-slices.
    const int jl = lane & 7;
    const int ks = lane >> 3;
    // Level-1 lane layout (warps 8-11): 16 neurons/warp, 2 k-halves.
    const int jn = lane & 15;
    const int kh = lane >> 4;

    const int j  = isL0 ? (warp * 8 + jl) : ((warp - 8) * 16 + jn); // 0..63
    const int jf = (int)rank * 64 + j;                              // 0..255

    const uint32_t mb_u32[2] = { smem_u32(&S->mbar[0]), smem_u32(&S->mbar[1]) };
    if (tid == 0) {
        asm volatile("mbarrier.init.shared.b64 [%0], 1;" :: "r"(mb_u32[0]) : "memory");
        asm volatile("mbarrier.init.shared.b64 [%0], 1;" :: "r"(mb_u32[1]) : "memory");
    }

    // Zero all h buffers (h1(-1)=0 relies on this).
    for (int e = tid; e < 3 * CS * BLK2; e += NT)
        ((float*)S->hb)[e] = 0.f;

    // Preload level-1 weights into SMEM, pk2-packed, [kq][j] layout.
    for (int idx = tid; idx < 64 * 64; idx += NT) {
        const int kq = idx >> 6;        // 0..63 (k = 4*kq .. 4*kq+3)
        const int jj = idx & 63;        // local neuron
        const int g  = ((int)rank * 64 + jj) * 256 + kq * 4;
        float4 wv = __ldg((const float4*)(Wi1 + g));
        ulonglong2 e;
        e.x = pk2(wv.x, wv.y); e.y = pk2(wv.z, wv.w);
        S->wqi[kq][jj] = e;
        float4 av = __ldg((const float4*)(Wr1 + g));
        float4 mv = __ldg((const float4*)(M1  + g));
        e.x = pk2(av.x * mv.x, av.y * mv.y);
        e.y = pk2(av.z * mv.z, av.w * mv.w);
        S->wqa[kq][jj] = e;
    }

    int32_t dsd[CS];
    #pragma unroll
    for (int c = 0; c < CS; c++) {
        uint32_t ra;
        asm("mapa.shared::cluster.u32 %0, %1, %2;" : "=r"(ra) : "r"(mb_u32[0]), "r"(c));
        dsd[c] = (int32_t)(ra - mb_u32[0]);
    }

    // Level-0 recurrent weights in registers (masked), k in [ks*64, +64).
    u64t wa0[32];
    if (isL0) {
        const float4* wr = (const float4*)(Wr0 + (size_t)jf * HH + ks * 64);
        const float4* mr = (const float4*)(M0  + (size_t)jf * HH + ks * 64);
        #pragma unroll
        for (int ii = 0; ii < 16; ii++) {
            float4 wv = __ldg(wr + ii);
            float4 mv = __ldg(mr + ii);
            wa0[2 * ii + 0] = pk2(wv.x * mv.x, wv.y * mv.y);
            wa0[2 * ii + 1] = pk2(wv.z * mv.z, wv.w * mv.w);
        }
    }

    const float invtau = 1.0f / (log1pf(expf((isL0 ? T0 : T1)[jf])) + 0.1f);
    const float bias1  = isL0 ? 0.f : __ldg(B1 + jf);

    const float* xp0 = g_xp + (size_t)(b0 * TT) * HH + jf;
    const float* xp1 = g_xp + (size_t)(b1 * TT) * HH + jf;
    float* o00 = out + (size_t)(b0 * TT) * 512 + jf;
    float* o01 = out + (size_t)(b1 * TT) * 512 + jf;
    float* o10 = out + (size_t)(b0 * TT) * 512 + 256 + jf;
    float* o11 = out + (size_t)(b1 * TT) * 512 + 256 + jf;

    __syncthreads();
    asm volatile("barrier.cluster.arrive.aligned;" ::: "memory");
    asm volatile("barrier.cluster.wait.aligned;"   ::: "memory");

    float xq0 = 0.f, xq1 = 0.f;
    if (isL0) { xq0 = __ldg(xp0); xq1 = __ldg(xp1); }

    int wb = 0, rb = 2;

    for (int t = 0; t < TT; t++) {
        const uint32_t mbx = mb_u32[t & 1];
        if (tid == 0)
            asm volatile("mbarrier.arrive.expect_tx.shared.b64 _, [%0], 3072;"
                         :: "r"(mbx) : "memory");

        const float* rblk = &S->hb[rb][rank][0];
        float* wblk = &S->hb[wb][rank][0];

        if (isL0) {
            // ---- Level-0 chain: h0(t) from h0(t-1) ----
            const float h0oa = rblk[j];
            const float h0ob = rblk[64 + j];
            const ulonglong2* p0 = (const ulonglong2*)(&S->hb[rb][ks][0]);
            const ulonglong2* p1 = (const ulonglong2*)(&S->hb[rb][ks][64]);
            u64t a0 = 0, a1 = 0, c0 = 0, c1 = 0;
            #pragma unroll
            for (int ii = 0; ii < 16; ii++) {
                ulonglong2 v0 = p0[ii];
                ulonglong2 v1 = p1[ii];
                fma2(a0, wa0[2 * ii + 0], v0.x);
                fma2(a1, wa0[2 * ii + 1], v0.y);
                fma2(c0, wa0[2 * ii + 0], v1.x);
                fma2(c1, wa0[2 * ii + 1], v1.y);
            }
            float s0 = hsum2(a0) + hsum2(a1);
            float s1 = hsum2(c0) + hsum2(c1);
            s0 += __shfl_xor_sync(0xffffffffu, s0, 8);
            s0 += __shfl_xor_sync(0xffffffffu, s0, 16);
            s1 += __shfl_xor_sync(0xffffffffu, s1, 8);
            s1 += __shfl_xor_sync(0xffffffffu, s1, 16);

            float hn0a = fmaf(tanh_fast(s0 + xq0) - h0oa, invtau, h0oa);
            float hn0b = fmaf(tanh_fast(s1 + xq1) - h0ob, invtau, h0ob);

            if (ks == 0) {
                wblk[j]      = hn0a;
                wblk[64 + j] = hn0b;
            }
            __syncthreads();

            if (tid < 3) {
                asm volatile("fence.proxy.async.shared::cta;" ::: "memory");
                const uint32_t src  = smem_u32(wblk);
                const int      peer = ((int)rank + tid + 1) & 3;
                asm volatile(
                    "cp.async.bulk.shared::cluster.shared::cta.mbarrier::complete_tx::bytes "
                    "[%0], [%1], 1024, [%2];"
                    :: "r"(src + dsd[peer]), "r"(src), "r"(mbx + dsd[peer])
                    : "memory");
            }

            if (ks == 1) o00[(size_t)t * 512] = hn0a;
            if (ks == 2) o01[(size_t)t * 512] = hn0b;
            if (t + 1 < TT) {
                xq0 = __ldg(xp0 + (size_t)(t + 1) * HH);
                xq1 = __ldg(xp1 + (size_t)(t + 1) * HH);
            }
        } else {
            // ---- Level-1 chain: h1(t-1) from h1(t-2), h0(t-1) ----
            float hn1a = 0.f, hn1b = 0.f;
            if (t > 0) {
                const float h1oa = rblk[128 + j];
                const float h1ob = rblk[192 + j];
                u64t A0 = 0, A1 = 0, B0 = 0, B1v = 0;
                #pragma unroll
                for (int half = 0; half < 2; half++) {
                    const float* blk = &S->hb[rb][2 * kh + half][0];
                    const ulonglong2* p0 = (const ulonglong2*)(blk);        // h0 b0
                    const ulonglong2* p1 = (const ulonglong2*)(blk + 64);   // h0 b1
                    const ulonglong2* q0 = (const ulonglong2*)(blk + 128);  // h1 b0
                    const ulonglong2* q1 = (const ulonglong2*)(blk + 192);  // h1 b1
                    const int krow = kh * 32 + half * 16;
                    #pragma unroll
                    for (int ii = 0; ii < 16; ii++) {
                        ulonglong2 wv = S->wqi[krow + ii][j];
                        ulonglong2 v0 = p0[ii];
                        ulonglong2 v1 = p1[ii];
                        fma2(A0, wv.x, v0.x); fma2(A1, wv.y, v0.y);
                        fma2(B0, wv.x, v1.x); fma2(B1v, wv.y, v1.y);
                        ulonglong2 aw = S->wqa[krow + ii][j];
                        ulonglong2 u0 = q0[ii];
                        ulonglong2 u1 = q1[ii];
                        fma2(A0, aw.x, u0.x); fma2(A1, aw.y, u0.y);
                        fma2(B0, aw.x, u1.x); fma2(B1v, aw.y, u1.y);
                    }
                }
                float s0 = hsum2(A0) + hsum2(A1);
                float s1 = hsum2(B0) + hsum2(B1v);
                s0 += __shfl_xor_sync(0xffffffffu, s0, 16);
                s1 += __shfl_xor_sync(0xffffffffu, s1, 16);

                hn1a = fmaf(tanh_fast(s0 + bias1) - h1oa, invtau, h1oa);
                hn1b = fmaf(tanh_fast(s1 + bias1) - h1ob, invtau, h1ob);

                if (kh == 0) {
                    wblk[128 + j] = hn1a;
                    wblk[192 + j] = hn1b;
                }
            }
            __syncthreads();

            if (t > 0) {
                if (kh == 0) o10[(size_t)(t - 1) * 512] = hn1a;
                else         o11[(size_t)(t - 1) * 512] = hn1b;
            }
        }

        mbar_wait(mbx, (uint32_t)((t >> 1) & 1));

        rb = wb;
        wb = (wb == 2) ? 0 : wb + 1;
    }

    // Epilogue: h1(127) from rb = {h0(127), h1(126)} (level-1 warps).
    if (!isL0) {
        const float* rblk = &S->hb[rb][rank][0];
        const float h1oa = rblk[128 + j];
        const float h1ob = rblk[192 + j];
        u64t A0 = 0, A1 = 0, B0 = 0, B1v = 0;
        #pragma unroll
        for (int half = 0; half < 2; half++) {
            const float* blk = &S->hb[rb][2 * kh + half][0];
            const ulonglong2* p0 = (const ulonglong2*)(blk);
            const ulonglong2* p1 = (const ulonglong2*)(blk + 64);
            const ulonglong2* q0 = (const ulonglong2*)(blk + 128);
            const ulonglong2* q1 = (const ulonglong2*)(blk + 192);
            const int krow = kh * 32 + half * 16;
            #pragma unroll
            for (int ii = 0; ii < 16; ii++) {
                ulonglong2 wv = S->wqi[krow + ii][j];
                ulonglong2 v0 = p0[ii];
                ulonglong2 v1 = p1[ii];
                fma2(A0, wv.x, v0.x); fma2(A1, wv.y, v0.y);
                fma2(B0, wv.x, v1.x); fma2(B1v, wv.y, v1.y);
                ulonglong2 aw = S->wqa[krow + ii][j];
                ulonglong2 u0 = q0[ii];
                ulonglong2 u1 = q1[ii];
                fma2(A0, aw.x, u0.x); fma2(A1, aw.y, u0.y);
                fma2(B0, aw.x, u1.x); fma2(B1v, aw.y, u1.y);
            }
        }
        float s0 = hsum2(A0) + hsum2(A1);
        float s1 = hsum2(B0) + hsum2(B1v);
        s0 += __shfl_xor_sync(0xffffffffu, s0, 16);
        s1 += __shfl_xor_sync(0xffffffffu, s1, 16);
        float hn1a = fmaf(tanh_fast(s0 + bias1) - h1oa, invtau, h1oa);
        float hn1b = fmaf(tanh_fast(s1 + bias1) - h1ob, invtau, h1ob);
        if (kh == 0) o10[(size_t)(TT - 1) * 512] = hn1a;
        else         o11[(size_t)(TT - 1) * 512] = hn1b;
    }

    // Nobody exits while peers' bulk reads of our SMEM may be in flight.
    asm volatile("barrier.cluster.arrive.aligned;" ::: "memory");
    asm volatile("barrier.cluster.wait.aligned;"   ::: "memory");
}

// ---------------------------------------------------------------------------
// Launch: gemm(xp0) -> warp-specialized combined 2-level scan
// ---------------------------------------------------------------------------
extern "C" void kernel_launch(void* const* d_in, const int* in_sizes, int n_in,
                              void* d_out, int out_size)
{
    const int*   tokens = (const int*)  d_in[0];
    const float* emb    = (const float*)d_in[1];
    const float* W_in0  = (const float*)d_in[2];
    const float* W_rec0 = (const float*)d_in[3];
    const float* b0     = (const float*)d_in[4];
    const float* tau0   = (const float*)d_in[5];
    const float* mask0  = (const float*)d_in[6];
    const float* W_in1  = (const float*)d_in[7];
    const float* W_rec1 = (const float*)d_in[8];
    const float* b1     = (const float*)d_in[9];
    const float* tau1   = (const float*)d_in[10];
    const float* mask1  = (const float*)d_in[11];
    float* out = (float*)d_out;

    (void)in_sizes; (void)n_in; (void)out_size;

    cudaFuncSetAttribute(ltc_scan2,
                         cudaFuncAttributeMaxDynamicSharedMemorySize, SMEM_SZ);

    dim3 ggrid(BT / 128, HH / 128);   // 64 x 2 = 128 CTAs (one wave)

    gemm_xp<<<ggrid, 256>>>(emb, tokens, EE, W_in0, b0);
    ltc_scan2<<<128, NT, SMEM_SZ>>>(W_rec0, mask0, tau0,
                                    W_rec1, mask1, tau1,
                                    W_in1, b1, out);
}